// round 9
// baseline (speedup 1.0000x reference)
#include <cuda_runtime.h>
#include <cuda_bf16.h>
#include <cstdint>

// out[n,p,:] = feat[n,p,:] * mean_m task[n,m,p]
// n=32, m=16, p=1024, d=512 (fp32)
//
// Warp-autonomous fused kernel + 256-bit memory ops + streaming (.cs)
// policy on BOTH streams.
// Rationale (R8 post-mortem): ncu cold-cache kernel time favors v8+default,
// but the harness's steady-state graph-replay timing favored .cs-both (R5).
// This combines the v8 instruction-count win with the .cs steady-state win:
// evict-first stores avoid write-allocate churn against the 126 MB L2,
// evict-first loads avoid futile feat retention across replays.

#define N_ 32
#define M_ 16
#define P_ 1024
#define D_ 512

#define TPB_ 256
#define ROWS_PER_BLK_ 16   // 8 warps x 2 rows

struct f8 { float v[8]; };

__device__ __forceinline__ f8 ldg256_cs(const float* p) {
    f8 r;
    asm("ld.global.cs.v8.b32 {%0,%1,%2,%3,%4,%5,%6,%7}, [%8];"
        : "=f"(r.v[0]), "=f"(r.v[1]), "=f"(r.v[2]), "=f"(r.v[3]),
          "=f"(r.v[4]), "=f"(r.v[5]), "=f"(r.v[6]), "=f"(r.v[7])
        : "l"(p));
    return r;
}

__device__ __forceinline__ void stg256_cs(float* p, const f8& r) {
    asm volatile("st.global.cs.v8.b32 [%0], {%1,%2,%3,%4,%5,%6,%7,%8};"
        :: "l"(p),
           "f"(r.v[0]), "f"(r.v[1]), "f"(r.v[2]), "f"(r.v[3]),
           "f"(r.v[4]), "f"(r.v[5]), "f"(r.v[6]), "f"(r.v[7])
        : "memory");
}

__global__ __launch_bounds__(TPB_, 8)
void MAP_fused_kernel(const float* __restrict__ task,
                      const float* __restrict__ feat,
                      float* __restrict__ out) {
    const int tid  = threadIdx.x;
    const int warp = tid >> 5;
    const int lane = tid & 31;

    const int rowA = blockIdx.x * ROWS_PER_BLK_ + warp * 2;  // global row n*P_+p
    const int n  = rowA >> 10;           // same n for the whole block (16 | 1024)
    const int p0 = rowA & (P_ - 1);

    // ---- task load (issued first: feeds the shuffle chain) ----
    const int m = lane & 15;             // 0..15
    const int pr = p0 + (lane >> 4);     // row A for lanes 0-15, row B for 16-31
    float tv = __ldg(task + (size_t)n * (M_ * P_) + m * P_ + pr);

    // ---- feat loads: 4 x 256-bit per thread (2 rows x 2 chunks) ----
    const float* fA = feat + (size_t)rowA * D_ + lane * 8;
    float*       oA = out  + (size_t)rowA * D_ + lane * 8;

    f8 va0 = ldg256_cs(fA);
    f8 va1 = ldg256_cs(fA + 256);
    f8 vb0 = ldg256_cs(fA + D_);
    f8 vb1 = ldg256_cs(fA + D_ + 256);

    // ---- segment reduce (width 16) -> both row means on every lane ----
    tv += __shfl_xor_sync(0xffffffffu, tv, 8, 16);
    tv += __shfl_xor_sync(0xffffffffu, tv, 4, 16);
    tv += __shfl_xor_sync(0xffffffffu, tv, 2, 16);
    tv += __shfl_xor_sync(0xffffffffu, tv, 1, 16);
    const float muA = __shfl_sync(0xffffffffu, tv, 0)  * (1.0f / (float)M_);
    const float muB = __shfl_sync(0xffffffffu, tv, 16) * (1.0f / (float)M_);

    // ---- scale + store (256-bit, evict-first) ----
#pragma unroll
    for (int j = 0; j < 8; ++j) va0.v[j] *= muA;
    stg256_cs(oA, va0);
#pragma unroll
    for (int j = 0; j < 8; ++j) va1.v[j] *= muA;
    stg256_cs(oA + 256, va1);
#pragma unroll
    for (int j = 0; j < 8; ++j) vb0.v[j] *= muB;
    stg256_cs(oA + D_, vb0);
#pragma unroll
    for (int j = 0; j < 8; ++j) vb1.v[j] *= muB;
    stg256_cs(oA + D_ + 256, vb1);
}

extern "C" void kernel_launch(void* const* d_in, const int* in_sizes, int n_in,
                              void* d_out, int out_size) {
    const float* task = (const float*)d_in[0];   // [32,16,1024]
    const float* feat = (const float*)d_in[1];   // [32,1024,512]
    float* out = (float*)d_out;                  // [32,1024,512]
    (void)in_sizes; (void)n_in; (void)out_size;

    const unsigned blocks = (N_ * P_) / ROWS_PER_BLK_;   // 2048
    MAP_fused_kernel<<<blocks, TPB_>>>(task, feat, out);
}

// round 10
// speedup vs baseline: 1.1807x; 1.1807x over previous
#include <cuda_runtime.h>
#include <cuda_bf16.h>
#include <cstdint>

// out[n,p,:] = feat[n,p,:] * mean_m task[n,m,p]
// n=32, m=16, p=1024, d=512 (fp32)
//
// Warp-autonomous fused kernel, 256-bit memory ops.
// Policy (from the R5-R9 matrix):
//  - loads:  ld.global.nc.v8 DEFAULT policy (R9 proved .cs loads are slow;
//            R8 proved default-nc is fastest: 18.7us)
//  - stores: st.global.cs.v8 evict-first (out is never re-read; avoid
//            write-allocate churn of 64 MB against the 126 MB L2)

#define N_ 32
#define M_ 16
#define P_ 1024
#define D_ 512

#define TPB_ 256
#define ROWS_PER_BLK_ 16   // 8 warps x 2 rows

struct f8 { float v[8]; };

__device__ __forceinline__ f8 ldg256(const float* p) {
    f8 r;
    asm("ld.global.nc.v8.b32 {%0,%1,%2,%3,%4,%5,%6,%7}, [%8];"
        : "=f"(r.v[0]), "=f"(r.v[1]), "=f"(r.v[2]), "=f"(r.v[3]),
          "=f"(r.v[4]), "=f"(r.v[5]), "=f"(r.v[6]), "=f"(r.v[7])
        : "l"(p));
    return r;
}

__device__ __forceinline__ void stg256_cs(float* p, const f8& r) {
    asm volatile("st.global.cs.v8.b32 [%0], {%1,%2,%3,%4,%5,%6,%7,%8};"
        :: "l"(p),
           "f"(r.v[0]), "f"(r.v[1]), "f"(r.v[2]), "f"(r.v[3]),
           "f"(r.v[4]), "f"(r.v[5]), "f"(r.v[6]), "f"(r.v[7])
        : "memory");
}

__global__ __launch_bounds__(TPB_, 8)
void MAP_fused_kernel(const float* __restrict__ task,
                      const float* __restrict__ feat,
                      float* __restrict__ out) {
    const int tid  = threadIdx.x;
    const int warp = tid >> 5;
    const int lane = tid & 31;

    const int rowA = blockIdx.x * ROWS_PER_BLK_ + warp * 2;  // global row n*P_+p
    const int n  = rowA >> 10;           // same n for the whole block (16 | 1024)
    const int p0 = rowA & (P_ - 1);

    // ---- task load (issued first: feeds the shuffle chain) ----
    const int m = lane & 15;             // 0..15
    const int pr = p0 + (lane >> 4);     // row A for lanes 0-15, row B for 16-31
    float tv = __ldg(task + (size_t)n * (M_ * P_) + m * P_ + pr);

    // ---- feat loads: 4 x 256-bit per thread (2 rows x 2 chunks) ----
    const float* fA = feat + (size_t)rowA * D_ + lane * 8;
    float*       oA = out  + (size_t)rowA * D_ + lane * 8;

    f8 va0 = ldg256(fA);
    f8 va1 = ldg256(fA + 256);
    f8 vb0 = ldg256(fA + D_);
    f8 vb1 = ldg256(fA + D_ + 256);

    // ---- segment reduce (width 16) -> both row means on every lane ----
    tv += __shfl_xor_sync(0xffffffffu, tv, 8, 16);
    tv += __shfl_xor_sync(0xffffffffu, tv, 4, 16);
    tv += __shfl_xor_sync(0xffffffffu, tv, 2, 16);
    tv += __shfl_xor_sync(0xffffffffu, tv, 1, 16);
    const float muA = __shfl_sync(0xffffffffu, tv, 0)  * (1.0f / (float)M_);
    const float muB = __shfl_sync(0xffffffffu, tv, 16) * (1.0f / (float)M_);

    // ---- scale + store (256-bit, evict-first stores) ----
#pragma unroll
    for (int j = 0; j < 8; ++j) va0.v[j] *= muA;
    stg256_cs(oA, va0);
#pragma unroll
    for (int j = 0; j < 8; ++j) va1.v[j] *= muA;
    stg256_cs(oA + 256, va1);
#pragma unroll
    for (int j = 0; j < 8; ++j) vb0.v[j] *= muB;
    stg256_cs(oA + D_, vb0);
#pragma unroll
    for (int j = 0; j < 8; ++j) vb1.v[j] *= muB;
    stg256_cs(oA + D_ + 256, vb1);
}

extern "C" void kernel_launch(void* const* d_in, const int* in_sizes, int n_in,
                              void* d_out, int out_size) {
    const float* task = (const float*)d_in[0];   // [32,16,1024]
    const float* feat = (const float*)d_in[1];   // [32,1024,512]
    float* out = (float*)d_out;                  // [32,1024,512]
    (void)in_sizes; (void)n_in; (void)out_size;

    const unsigned blocks = (N_ * P_) / ROWS_PER_BLK_;   // 2048
    MAP_fused_kernel<<<blocks, TPB_>>>(task, feat, out);
}

// round 11
// speedup vs baseline: 1.4484x; 1.2267x over previous
#include <cuda_runtime.h>
#include <cuda_bf16.h>

// out[n,p,:] = feat[n,p,:] * mean_m task[n,m,p]
// n=32, m=16, p=1024, d=512 (fp32)
//
// Warp-autonomous fused kernel, 128-bit (float4) memory ops.
// Width choice (R4-R10 matrix): v8 loads win ncu's cold single-launch but
// lose ~2.5us in the harness's steady-state replay loop (dur-kernel gap
// 1.9-2.2us for float4 kernels vs 3.8-4.8us for v8). dur is the scored
// metric -> float4 family.
// Policy: loads default-nc (__ldg; cs-loads proved harmful R9),
//         stores evict-first (__stcs; out never re-read).

#define N_ 32
#define M_ 16
#define P_ 1024
#define D_ 512

#define TPB_ 256
#define ROWS_PER_BLK_ 16   // 8 warps x 2 rows

__global__ __launch_bounds__(TPB_, 8)
void MAP_fused_kernel(const float* __restrict__ task,
                      const float* __restrict__ feat,
                      float* __restrict__ out) {
    const int tid  = threadIdx.x;
    const int warp = tid >> 5;
    const int lane = tid & 31;

    const int rowA = blockIdx.x * ROWS_PER_BLK_ + warp * 2;  // global row n*P_+p
    const int n  = rowA >> 10;           // same n for the whole block (16 | 1024)
    const int p0 = rowA & (P_ - 1);

    // ---- task load (issued first: feeds the shuffle chain) ----
    const int m = lane & 15;             // 0..15
    const int pr = p0 + (lane >> 4);     // row A for lanes 0-15, row B for 16-31
    float tv = __ldg(task + (size_t)n * (M_ * P_) + m * P_ + pr);

    // ---- feat loads (default policy; overlap task latency) ----
    const float4* f4 = reinterpret_cast<const float4*>(feat);
    float4*       o4 = reinterpret_cast<float4*>(out);
    const size_t a = (size_t)rowA * (D_ / 4) + lane;   // row A, this lane
    float4 va[4], vb[4];
#pragma unroll
    for (int j = 0; j < 4; ++j)
        va[j] = __ldg(f4 + a + j * 32);
#pragma unroll
    for (int j = 0; j < 4; ++j)
        vb[j] = __ldg(f4 + a + (D_ / 4) + j * 32);

    // ---- segment reduce (width 16) -> both row means on every lane ----
    tv += __shfl_xor_sync(0xffffffffu, tv, 8, 16);
    tv += __shfl_xor_sync(0xffffffffu, tv, 4, 16);
    tv += __shfl_xor_sync(0xffffffffu, tv, 2, 16);
    tv += __shfl_xor_sync(0xffffffffu, tv, 1, 16);
    const float muA = __shfl_sync(0xffffffffu, tv, 0)  * (1.0f / (float)M_);
    const float muB = __shfl_sync(0xffffffffu, tv, 16) * (1.0f / (float)M_);

    // ---- scale + store (evict-first) ----
#pragma unroll
    for (int j = 0; j < 4; ++j) {
        float4 r;
        r.x = va[j].x * muA; r.y = va[j].y * muA;
        r.z = va[j].z * muA; r.w = va[j].w * muA;
        __stcs(o4 + a + j * 32, r);
    }
#pragma unroll
    for (int j = 0; j < 4; ++j) {
        float4 r;
        r.x = vb[j].x * muB; r.y = vb[j].y * muB;
        r.z = vb[j].z * muB; r.w = vb[j].w * muB;
        __stcs(o4 + a + (D_ / 4) + j * 32, r);
    }
}

extern "C" void kernel_launch(void* const* d_in, const int* in_sizes, int n_in,
                              void* d_out, int out_size) {
    const float* task = (const float*)d_in[0];   // [32,16,1024]
    const float* feat = (const float*)d_in[1];   // [32,1024,512]
    float* out = (float*)d_out;                  // [32,1024,512]
    (void)in_sizes; (void)n_in; (void)out_size;

    const unsigned blocks = (N_ * P_) / ROWS_PER_BLK_;   // 2048
    MAP_fused_kernel<<<blocks, TPB_>>>(task, feat, out);
}